// round 6
// baseline (speedup 1.0000x reference)
#include <cuda_runtime.h>
#include <cstdint>

#define M_NODES   8192
#define K_PAR     8
#define C_CFG     256
#define N_LAYERS  8
#define TPB       128
#define NPB       16                          // nodes per block
#define TILE_B    (NPB * C_CFG * 4)           // 16384 bytes per block tile

__device__ __forceinline__ uint32_t smem_u32(const void* p) {
    uint32_t a;
    asm("{ .reg .u64 t; cvta.to.shared.u64 t, %1; cvt.u32.u64 %0, t; }"
        : "=r"(a) : "l"(p));
    return a;
}

__device__ __forceinline__ float fast_tanh(float x) {
    float r;
    asm("tanh.approx.f32 %0, %1;" : "=f"(r) : "f"(x));
    return r;
}

__device__ __forceinline__ float acc_sigmoid(float x) {
    float t = -1.4426950408889634f * x, e, r;
    asm("ex2.approx.f32 %0, %1;" : "=f"(e) : "f"(t));
    float d = 1.0f + e;
    asm("rcp.approx.f32 %0, %1;" : "=f"(r) : "f"(d));
    return r;
}

__device__ __forceinline__ void l2_prefetch_bulk(const void* p, uint32_t bytes) {
    asm volatile("cp.async.bulk.prefetch.L2.global [%0], %1;"
                 :: "l"(p), "r"(bytes) : "memory");
}

// Root: 64 blocks x 128 threads. Computes root marginals AND prefetches the
// whole layer-0 CPT (8 MB) into L2 (128 KB per block, fire-and-forget).
__global__ void __launch_bounds__(128)
root_kernel(const float* __restrict__ root_logits,
            const float* __restrict__ cpt0,
            float* __restrict__ out) {
    if (threadIdx.x == 0) {
        const char* base = reinterpret_cast<const char*>(cpt0)
                         + (size_t)blockIdx.x * (8 * TILE_B);
#pragma unroll
        for (int i = 0; i < 8; i++)
            l2_prefetch_bulk(base + i * TILE_B, TILE_B);
    }
    int i = blockIdx.x * 128 + threadIdx.x;
#pragma unroll
    for (int k = 0; k < M_NODES / (64 * 128); k++) {
        out[i] = acc_sigmoid(root_logits[i]);
        i += 64 * 128;
    }
}

// Block: 128 threads / 4 warps, 16 nodes. Own CPT tile via one TMA bulk copy;
// NEXT layer's same-index tile via L2 prefetch (overlaps everything).
// Fold mapping (validated R2-R5): config c = i*32 + gl*4 + t ; bit b <-> parent 7-b.
//   t bits 0-1  -> parents 7,6 (register folds)
//   gl bits 2-4 -> parents 5,4,3 (3x shfl_xor)
//   i bits 5-7  -> parents 2,1,0 (register folds)
// Folds run on tanh values (2*sigma-1); convex combos with total weight 1, so
// marginal = 0.5 + 0.5 * folded value.
__global__ void __launch_bounds__(TPB)
layer_kernel(const float* __restrict__ cpt,      // [M, C] this layer
             const float* __restrict__ cpt_next, // [M, C] next layer (or null)
             const int*   __restrict__ parents,  // [M, K]
             const float* __restrict__ prev,     // [M]
             float*       __restrict__ out)      // [M]
{
    __shared__ __align__(16) float tile[NPB * C_CFG];
    __shared__ __align__(8)  uint64_t mbar;

    const int tid    = threadIdx.x;
    const int lane   = tid & 31;
    const int wid    = tid >> 5;
    const int gl     = lane & 7;
    const int nlocal = wid * 4 + (lane >> 3);
    const int gwarp  = blockIdx.x * 4 + wid;
    const int pbase  = lane & 24;

    const uint32_t mbar_a = smem_u32(&mbar);
    if (tid == 0) {
        asm volatile("mbarrier.init.shared.b64 [%0], 1;" :: "r"(mbar_a) : "memory");
        asm volatile("fence.proxy.async.shared::cta;" ::: "memory");
    }
    __syncthreads();
    if (tid == 0) {
        asm volatile("mbarrier.arrive.expect_tx.shared.b64 _, [%0], %1;"
                     :: "r"(mbar_a), "r"((uint32_t)TILE_B) : "memory");
        asm volatile(
            "cp.async.bulk.shared::cta.global.mbarrier::complete_tx::bytes "
            "[%0], [%1], %2, [%3];"
            :: "r"(smem_u32(tile)),
               "l"(cpt + (size_t)blockIdx.x * (NPB * C_CFG)),
               "r"((uint32_t)TILE_B), "r"(mbar_a)
            : "memory");
        // Fire-and-forget: pull next layer's tile into L2 while we work.
        if (cpt_next)
            l2_prefetch_bulk(cpt_next + (size_t)blockIdx.x * (NPB * C_CFG),
                             TILE_B);
    }

    // Parent gather overlaps the TMA transfer.
    const int   pidx = parents[gwarp * 32 + lane];
    const float pp   = prev[pidx];
    float p[8];
#pragma unroll
    for (int j = 0; j < 8; j++)
        p[j] = __shfl_sync(0xffffffffu, pp, pbase | j);

    // Wait for own CPT tile (parity 0).
    {
        uint32_t done;
        asm volatile(
            "{\n\t.reg .pred q;\n\t"
            "mbarrier.try_wait.parity.shared.b64 q, [%1], 0;\n\t"
            "selp.b32 %0, 1, 0, q;\n\t}"
            : "=r"(done) : "r"(mbar_a) : "memory");
        while (!done) {
            asm volatile(
                "{\n\t.reg .pred q;\n\t"
                "mbarrier.try_wait.parity.shared.b64 q, [%1], 0, 1000000;\n\t"
                "selp.b32 %0, 1, 0, q;\n\t}"
                : "=r"(done) : "r"(mbar_a) : "memory");
        }
    }

    // LDS + tanh + folds.
    const float4* row = reinterpret_cast<const float4*>(tile + nlocal * C_CFG) + gl;
    float r_i[8];
#pragma unroll
    for (int i = 0; i < 8; i++) {
        float4 v = row[i * 8];                 // configs i*32 + gl*4 .. +3
        float s0 = fast_tanh(0.5f * v.x);
        float s1 = fast_tanh(0.5f * v.y);
        float s2 = fast_tanh(0.5f * v.z);
        float s3 = fast_tanh(0.5f * v.w);
        float t0 = fmaf(p[7], s1 - s0, s0);
        float t1 = fmaf(p[7], s3 - s2, s2);
        r_i[i]   = fmaf(p[6], t1 - t0, t0);
    }
    float q0 = fmaf(p[2], r_i[1] - r_i[0], r_i[0]);
    float q1 = fmaf(p[2], r_i[3] - r_i[2], r_i[2]);
    float q2 = fmaf(p[2], r_i[5] - r_i[4], r_i[4]);
    float q3 = fmaf(p[2], r_i[7] - r_i[6], r_i[6]);
    float h0 = fmaf(p[1], q1 - q0, q0);
    float h1 = fmaf(p[1], q3 - q2, q2);
    float r  = fmaf(p[0], h1 - h0, h0);

#pragma unroll
    for (int b = 0; b < 3; b++) {
        int   msk = 1 << b;
        float o   = __shfl_xor_sync(0xffffffffu, r, msk);
        float a0  = (lane & msk) ? o : r;
        float a1  = (lane & msk) ? r : o;
        r = fmaf(p[5 - b], a1 - a0, a0);
    }

    if (gl == 0)
        out[blockIdx.x * NPB + nlocal] = fmaf(0.5f, r, 0.5f);
}

extern "C" void kernel_launch(void* const* d_in, const int* in_sizes, int n_in,
                              void* d_out, int out_size) {
    const float* root    = (const float*)d_in[0];  // [M]
    const float* cpt     = (const float*)d_in[1];  // [L, M, C]
    const int*   parents = (const int*)  d_in[2];  // [L, M, K]
    float*       out     = (float*)d_out;          // [(L+1)*M]

    root_kernel<<<64, 128>>>(root, cpt, out);

    for (int l = 0; l < N_LAYERS; l++) {
        const float* next = (l + 1 < N_LAYERS)
            ? cpt + (size_t)(l + 1) * M_NODES * C_CFG : nullptr;
        layer_kernel<<<M_NODES / NPB, TPB>>>(
            cpt     + (size_t)l * M_NODES * C_CFG,
            next,
            parents + (size_t)l * M_NODES * K_PAR,
            out     + (size_t)l * M_NODES,
            out     + (size_t)(l + 1) * M_NODES);
    }
}